// round 15
// baseline (speedup 1.0000x reference)
#include <cuda_runtime.h>
#include <cuda_bf16.h>
#include <cstdint>

#define BB    8192
#define NVV   778
#define NJJ   16
#define CTOT  2334
#define CPAD  2496          // 13 * 192
#define GK    160           // padded K (145 feat + 15 pad)
#define NVP   832           // 13 * 64 padded verts

// ---------------- device scratch (static; no runtime alloc) ----------------
__device__ __align__(16) float          g_V[(size_t)BB * CPAD];      // GEMM out + bias
__device__ __align__(16) __nv_bfloat16  g_A[BB * GK];
__device__ __align__(16) __nv_bfloat16  g_B[CPAD * GK];              // B^T [n][k]
__device__ __align__(16) __nv_bfloat16  g_Whi[NVP * 16];             // lbs hi/lo
__device__ __align__(16) __nv_bfloat16  g_Wlo[NVP * 16];
__device__ __align__(16) __nv_bfloat16  g_MH[(size_t)BB * 12 * 16];  // M'' hi [(b*12+m)*16+j]
__device__ __align__(16) __nv_bfloat16  g_ML[(size_t)BB * 12 * 16];  // M'' lo
__device__ __align__(16) float g_J0[NJJ * 3];
__device__ __align__(16) float g_JS[NJJ * 3 * 10];

__constant__ int c_par[16] = {0,0,1,2,0,4,5,0,7,8,0,10,11,0,13,14};
__constant__ int c_inv[16] = {0,5,6,7,9,10,11,17,18,19,13,14,15,1,2,3};

__device__ __forceinline__ void mma16816(float* d, const uint32_t* a,
                                         uint32_t b0, uint32_t b1) {
    asm volatile(
        "mma.sync.aligned.m16n8k16.row.col.f32.bf16.bf16.f32 "
        "{%0,%1,%2,%3}, {%4,%5,%6,%7}, {%8,%9}, {%0,%1,%2,%3};"
        : "+f"(d[0]), "+f"(d[1]), "+f"(d[2]), "+f"(d[3])
        : "r"(a[0]), "r"(a[1]), "r"(a[2]), "r"(a[3]), "r"(b0), "r"(b1));
}

__device__ __forceinline__ void ldsm4(uint32_t* r, uint32_t addr) {
    asm volatile("ldmatrix.sync.aligned.m8n8.x4.shared.b16 {%0,%1,%2,%3}, [%4];"
        : "=r"(r[0]), "=r"(r[1]), "=r"(r[2]), "=r"(r[3]) : "r"(addr));
}

__device__ __forceinline__ uint32_t smem_u32(const void* p) {
    uint32_t a;
    asm("{ .reg .u64 t; cvta.to.shared.u64 t, %1; cvt.u32.u64 %0, t; }"
        : "=r"(a) : "l"(p));
    return a;
}
// L1-bypassing 16B async copy
__device__ __forceinline__ void cpasync16(uint32_t dst, const void* src) {
    asm volatile("cp.async.cg.shared.global [%0], [%1], 16;"
                 :: "r"(dst), "l"(src));
}
#define CP_COMMIT()  asm volatile("cp.async.commit_group;" ::: "memory")
#define CP_WAIT(n)   asm volatile("cp.async.wait_group %0;" :: "n"(n) : "memory")

// ---------------------------------------------------------------------------
// K0_SMALL: [0,16): jreg contractions; [16,68): lbs hi/lo split
// ---------------------------------------------------------------------------
__global__ __launch_bounds__(256) void k0_small(const float* __restrict__ vt,
                                                const float* __restrict__ sd,
                                                const float* __restrict__ jreg,
                                                const float* __restrict__ lbs) {
    __shared__ float red[33 * 256];
    const int blk = blockIdx.x, tid = threadIdx.x;

    if (blk >= 16) {                        // ---- lbs hi/lo
        int idx = (blk - 16) * 256 + tid;
        if (idx >= NVP * 16) return;
        int v = idx >> 4, j = idx & 15;
        float w = (v < NVV) ? lbs[v * 16 + j] : 0.f;
        __nv_bfloat16 hi = __float2bfloat16_rn(w);
        __nv_bfloat16 lo = __float2bfloat16_rn(w - __bfloat162float(hi));
        g_Whi[idx] = hi;
        g_Wlo[idx] = lo;
        return;
    }
    // ---- joint regressor: one block per joint
    const int j = blk;
    float acc[33];
#pragma unroll
    for (int o = 0; o < 33; o++) acc[o] = 0.f;
    for (int v = tid; v < NVV; v += 256) {
        float w = jreg[j * NVV + v];
#pragma unroll
        for (int k = 0; k < 3; k++) {
            acc[k] += w * vt[v * 3 + k];
#pragma unroll
            for (int l = 0; l < 10; l++)
                acc[3 + k * 10 + l] += w * sd[(v * 3 + k) * 10 + l];
        }
    }
    for (int o = 0; o < 33; o++) red[o * 256 + tid] = acc[o];
    __syncthreads();
    if (tid < 33) {
        float s = 0.f;
        for (int i = 0; i < 256; i++) s += red[tid * 256 + i];
        if (tid < 3) g_J0[j * 3 + tid] = s;
        else {
            int o = tid - 3;
            int k = o / 10, l = o - k * 10;
            g_JS[(j * 3 + k) * 10 + l] = s;
        }
    }
}

// ---------------------------------------------------------------------------
// K0_AB: [0,640): A (8 elems/thread, 20 groups/row); [640,840): B
// ---------------------------------------------------------------------------
__global__ __launch_bounds__(256) void k0_AB(const float* __restrict__ sd,
                                             const float* __restrict__ pd,
                                             const float* __restrict__ shape,
                                             const float* __restrict__ finger) {
    const int blk = blockIdx.x, tid = threadIdx.x;

    if (blk < 640) {                        // ---- A: feat bf16 [B x 160], 8/thr
        int idx = blk * 256 + tid;          // < 163840
        int b = idx / 20, g = idx - b * 20;
        unsigned short hs[8];
#pragma unroll
        for (int i = 0; i < 8; i++) {
            int k = g * 8 + i;
            float val = 0.f;
            if (k < 10) val = shape[b * 10 + k];
            else if (k < 145) {
                int q = k - 10;
                val = finger[b * 135 + q];
                if (((q % 9) & 3) == 0) val -= 1.0f;
            }
            hs[i] = __bfloat16_as_ushort(__float2bfloat16_rn(val));
        }
        uint4 ph;
        ph.x = hs[0] | ((uint32_t)hs[1] << 16);
        ph.y = hs[2] | ((uint32_t)hs[3] << 16);
        ph.z = hs[4] | ((uint32_t)hs[5] << 16);
        ph.w = hs[6] | ((uint32_t)hs[7] << 16);
        *reinterpret_cast<uint4*>(&g_A[b * GK + g * 8]) = ph;
        return;
    }
    // ---- B^T bf16 [n][k]
    int q = blk - 640;
    int kg = q / 10, nb = q - kg * 10;      // kg 0..19
    int n = nb * 256 + tid;
    if (n >= CPAD) return;
    unsigned short hs[8];
#pragma unroll
    for (int i = 0; i < 8; i++) {
        int k = kg * 8 + i;
        float val = 0.f;
        if (n < CTOT) {
            if (k < 10)       val = sd[n * 10 + k];
            else if (k < 145) val = pd[(k - 10) * CTOT + n];
        }
        hs[i] = __bfloat16_as_ushort(__float2bfloat16_rn(val));
    }
    uint4 ph;
    ph.x = hs[0] | ((uint32_t)hs[1] << 16);
    ph.y = hs[2] | ((uint32_t)hs[3] << 16);
    ph.z = hs[4] | ((uint32_t)hs[5] << 16);
    ph.w = hs[6] | ((uint32_t)hs[7] << 16);
    *reinterpret_cast<uint4*>(&g_B[n * GK + kg * 8]) = ph;
}

// ---------------------------------------------------------------------------
// K2: joint chain — 4 batches per CTA; writes M'' as split-bf16 (b*12+m)x16
// ---------------------------------------------------------------------------
__device__ __forceinline__ void mul4(const float* a, float* d) {
    float t[16];
#pragma unroll
    for (int r = 0; r < 4; r++)
#pragma unroll
        for (int c = 0; c < 4; c++)
            t[r * 4 + c] = a[r * 4 + 0] * d[0 + c] + a[r * 4 + 1] * d[4 + c] +
                           a[r * 4 + 2] * d[8 + c] + a[r * 4 + 3] * d[12 + c];
#pragma unroll
    for (int i = 0; i < 16; i++) d[i] = t[i];
}

__global__ __launch_bounds__(256) void k2_joints(const float* __restrict__ grmt,
                          const float* __restrict__ frmt,
                          const float* __restrict__ shape,
                          const float* __restrict__ trans,
                          float* __restrict__ outJ) {
    __shared__ float sJ[4][16][3];
    __shared__ float sM[4][16][16];
    __shared__ float sF[4][136];
    __shared__ float sg[4][9], st[4][3], ssh[4][10];
    const int tid = threadIdx.x;
    const int bs = tid >> 6;
    const int tl = tid & 63;
    const int b = blockIdx.x * 4 + bs;
    const int b0 = blockIdx.x * 4;

    for (int i = tid; i < 540; i += 256) {
        int s = i / 135, q = i - s * 135;
        sF[s][q] = frmt[(b0 + s) * 135 + q];
    }
    if (tl < 9)  sg[bs][tl]  = grmt[b * 9 + tl];
    if (tl < 3)  st[bs][tl]  = trans[b * 3 + tl];
    if (tl < 10) ssh[bs][tl] = shape[b * 10 + tl];
    __syncthreads();

    if (tl < 48) {
        int j = tl / 3, k = tl - j * 3;
        float a = g_J0[j * 3 + k];
#pragma unroll
        for (int l = 0; l < 10; l++) a += ssh[bs][l] * g_JS[(j * 3 + k) * 10 + l];
        sJ[bs][j][k] = a;
    }
    __syncthreads();

    if (tl < 16) {
        int j = tl;
        float R[9];
        if (j == 0) {
            R[0]=1;R[1]=0;R[2]=0;R[3]=0;R[4]=1;R[5]=0;R[6]=0;R[7]=0;R[8]=1;
        } else {
#pragma unroll
            for (int i = 0; i < 9; i++) R[i] = sF[bs][(j - 1) * 9 + i];
        }
        float t0 = sJ[bs][j][0], t1 = sJ[bs][j][1], t2 = sJ[bs][j][2];
        if (j > 0) {
            int p = c_par[j];
            t0 -= sJ[bs][p][0]; t1 -= sJ[bs][p][1]; t2 -= sJ[bs][p][2];
        }
        float* m = sM[bs][j];
        m[0]=R[0]; m[1]=R[1]; m[2]=R[2];  m[3]=t0;
        m[4]=R[3]; m[5]=R[4]; m[6]=R[5];  m[7]=t1;
        m[8]=R[6]; m[9]=R[7]; m[10]=R[8]; m[11]=t2;
        m[12]=0.f; m[13]=0.f; m[14]=0.f;  m[15]=1.f;
    }
    __syncthreads();

    if (tl < 5) {
        int j = 1 + 3 * tl;
        mul4(sM[bs][0], sM[bs][j]);
        mul4(sM[bs][j], sM[bs][j + 1]);
        mul4(sM[bs][j + 1], sM[bs][j + 2]);
    }
    __syncthreads();

    if (tl < 16) {
        int j = tl;
        const float* m = sM[bs][j];
        float jt0 = m[3], jt1 = m[7], jt2 = m[11];
        float J0 = sJ[bs][j][0], J1 = sJ[bs][j][1], J2 = sJ[bs][j][2];
        float tc0 = jt0 - (m[0] * J0 + m[1] * J1 + m[2]  * J2);
        float tc1 = jt1 - (m[4] * J0 + m[5] * J1 + m[6]  * J2);
        float tc2 = jt2 - (m[8] * J0 + m[9] * J1 + m[10] * J2);
        float row[12];
        int jp = c_inv[j];
#pragma unroll
        for (int r = 0; r < 3; r++) {
            float a = sg[bs][r * 3 + 0], bb = sg[bs][r * 3 + 1], cc = sg[bs][r * 3 + 2];
            row[r * 4 + 0] = a * m[0] + bb * m[4] + cc * m[8];
            row[r * 4 + 1] = a * m[1] + bb * m[5] + cc * m[9];
            row[r * 4 + 2] = a * m[2] + bb * m[6] + cc * m[10];
            row[r * 4 + 3] = a * tc0  + bb * tc1  + cc * tc2 + st[bs][r];
            outJ[(b * 21 + jp) * 3 + r] = a * jt0 + bb * jt1 + cc * jt2 + st[bs][r];
        }
#pragma unroll
        for (int mm = 0; mm < 12; mm++) {
            float x = row[mm];
            __nv_bfloat16 hi = __float2bfloat16_rn(x);
            __nv_bfloat16 lo = __float2bfloat16_rn(x - __bfloat162float(hi));
            size_t off = ((size_t)b * 12 + mm) * 16 + j;
            g_MH[off] = hi;
            g_ML[off] = lo;
        }
    }
}

// ---------------------------------------------------------------------------
// K3: single-stage full-K bf16 GEMM with ldmatrix fragment loads.
//   CTA: 256 thr, tile 64(b) x 192(n), K=160 (10 ks steps). 2 CTAs/SM.
//   smem: A 64 x 336B @0 (21504); B 192 x 336B @21504 (64512) = 86016
//   Row stride 336B: LDSM phases hit distinct 16B banks (336 mod 128 = 80,
//   8-row orbit {0,80,32,112,64,16,96,48}) — conflict-free.
// ---------------------------------------------------------------------------
#define ASTR   336
#define BOFF   21504
#define SM_K3  86016

__global__ __launch_bounds__(256, 2) void k3_gemm(const float* __restrict__ vt) {
    extern __shared__ __align__(16) char smem[];
    __shared__ float sBias[192];
    const uint32_t sbase = smem_u32(smem);
    const int tid = threadIdx.x;
    const int wid = tid >> 5, lane = tid & 31;
    const int wm = wid & 1, wn = wid >> 1;      // 2 m-warps x 4 n-warps
    const int gid = lane >> 2, tig = lane & 3;
    const int b0 = blockIdx.x * 64;
    const int t  = blockIdx.y;

    if (tid < 192) {
        int c = t * 192 + tid;
        sBias[tid] = (c < CTOT) ? vt[c] : 0.f;
    }

    // ---- stage full K: A 1280 + B 3840 = 5120 uint4 tasks ----
    for (int i = tid; i < 5120; i += 256) {
        if (i < 1280) {
            int r = i / 20, q = i - r * 20;
            cpasync16(sbase + r * ASTR + q * 16,
                      &g_A[(b0 + r) * GK + q * 8]);
        } else {
            int i2 = i - 1280;
            int r = i2 / 20, q = i2 - r * 20;
            cpasync16(sbase + BOFF + r * ASTR + q * 16,
                      &g_B[(t * 192 + r) * GK + q * 8]);
        }
    }
    CP_COMMIT();
    CP_WAIT(0);
    __syncthreads();

    // ---- ldmatrix base addresses (per-lane) ----
    const int lrow  = (lane & 7) + ((lane >> 3) & 1) * 8;  // 0..15
    const int khalf = (lane >> 4) & 1;                     // 0/1 -> +16B
    uint32_t aAddr[2], bAddr[3];
#pragma unroll
    for (int mt = 0; mt < 2; mt++)
        aAddr[mt] = sbase + (uint32_t)(wm * 32 + mt * 16 + lrow) * ASTR +
                    khalf * 16;
#pragma unroll
    for (int p = 0; p < 3; p++)
        bAddr[p] = sbase + BOFF +
                   (uint32_t)(wn * 48 + p * 16 + lrow) * ASTR + khalf * 16;

    float d[2][6][4];
#pragma unroll
    for (int mt = 0; mt < 2; mt++)
#pragma unroll
        for (int nt = 0; nt < 6; nt++)
#pragma unroll
            for (int q = 0; q < 4; q++) d[mt][nt][q] = 0.f;

#pragma unroll
    for (int ks = 0; ks < 10; ks++) {
        const uint32_t kb = ks * 32;
        uint32_t a[2][4];
        ldsm4(a[0], aAddr[0] + kb);
        ldsm4(a[1], aAddr[1] + kb);
        uint32_t bm[3][4];
        ldsm4(bm[0], bAddr[0] + kb);
        ldsm4(bm[1], bAddr[1] + kb);
        ldsm4(bm[2], bAddr[2] + kb);
        // pair p covers nt = 2p (frag r0,r2) and nt = 2p+1 (frag r1,r3)
#pragma unroll
        for (int mt = 0; mt < 2; mt++)
#pragma unroll
            for (int p = 0; p < 3; p++) {
                mma16816(d[mt][2 * p],     a[mt], bm[p][0], bm[p][2]);
                mma16816(d[mt][2 * p + 1], a[mt], bm[p][1], bm[p][3]);
            }
    }

    // ---- writeout (+fp32 bias) ----
#pragma unroll
    for (int mt = 0; mt < 2; mt++) {
        int r0 = b0 + wm * 32 + mt * 16 + gid;
#pragma unroll
        for (int nt = 0; nt < 6; nt++) {
            int cl = wn * 48 + nt * 8 + tig * 2;
            int c = t * 192 + cl;
            float bx = sBias[cl], by = sBias[cl + 1];
            *reinterpret_cast<float2*>(&g_V[(size_t)r0 * CPAD + c]) =
                make_float2(d[mt][nt][0] + bx, d[mt][nt][1] + by);
            *reinterpret_cast<float2*>(&g_V[(size_t)(r0 + 8) * CPAD + c]) =
                make_float2(d[mt][nt][2] + bx, d[mt][nt][3] + by);
        }
    }
}

// ---------------------------------------------------------------------------
// K4: warp-autonomous LBS blend, 4 CTAs/SM (unchanged from R14)
// ---------------------------------------------------------------------------
#define SM_K4 46080

__global__ __launch_bounds__(256, 4) void k4_epi(float* __restrict__ outV,
                                                 float* __restrict__ outJ) {
    extern __shared__ __align__(16) char smem[];
    const uint32_t sbase = smem_u32(smem);
    __nv_bfloat16* sMh = reinterpret_cast<__nv_bfloat16*>(smem);
    __nv_bfloat16* sMl = reinterpret_cast<__nv_bfloat16*>(smem + 6144);

    const int tid = threadIdx.x;
    const int b0 = blockIdx.x * 16;
    const int y  = blockIdx.y;
    const int tstart = (y == 0) ? 0 : 1 + y * 3;      // {0,4,7,10}
    const int tend   = tstart + ((y == 0) ? 4 : 3);   // {4,7,10,13}

    auto stage_W = [&](int s, int t) {
        int split = tid >> 7, i2 = tid & 127;
        int row = i2 >> 1, half = i2 & 1;
        const __nv_bfloat16* src = split ? g_Wlo : g_Whi;
        cpasync16(sbase + 13312 + s * 4096 + split * 2048 +
                      (row * 16 + half * 8) * 2,
                  &src[(t * 64 + row) * 16 + half * 8]);
    };
    auto stage_V = [&](int s, int t) {
        for (int i = tid; i < 768; i += 256) {
            int r = i / 48, q = i - r * 48;
            cpasync16(sbase + 21504 + s * 12288 + (r * 192 + q * 4) * 4,
                      &g_V[(size_t)(b0 + r) * CPAD + t * 192 + q * 4]);
        }
    };

    // stage M'' (12KB into region A) + first W and V slices
    for (int i = tid; i < 768; i += 256) {
        int split = i / 384, i2 = i - split * 384;
        int n = i2 >> 1, half = i2 & 1;
        const __nv_bfloat16* src = split ? g_ML : g_MH;
        cpasync16(sbase + split * 6144 + (n * 16 + half * 8) * 2,
                  &src[((size_t)b0 * 12 + n) * 16 + half * 8]);
    }
    stage_W(0, tstart);
    stage_V(0, tstart);
    CP_COMMIT();
    CP_WAIT(0);
    __syncthreads();

    const int wid = tid >> 5, lane = tid & 31;
    const int gid = lane >> 2, tig = lane & 3;
    float* strip = reinterpret_cast<float*>(smem + wid * 1664);  // region A reuse
    const int half = lane >> 4, lv = lane & 15;
    const int bq = wid * 2 + half;
    const int bglob = b0 + bq;

    // hoist B fragments (M'' columns) — tile-invariant
    uint32_t fbh[3][2], fbl[3][2];
#pragma unroll
    for (int ntl = 0; ntl < 3; ntl++) {
        int n0 = wid * 24 + ntl * 8 + gid;
        fbh[ntl][0] = *reinterpret_cast<const uint32_t*>(&sMh[n0 * 16 + tig * 2]);
        fbh[ntl][1] = *reinterpret_cast<const uint32_t*>(&sMh[n0 * 16 + 8 + tig * 2]);
        fbl[ntl][0] = *reinterpret_cast<const uint32_t*>(&sMl[n0 * 16 + tig * 2]);
        fbl[ntl][1] = *reinterpret_cast<const uint32_t*>(&sMl[n0 * 16 + 8 + tig * 2]);
    }
    __syncthreads();   // all M'' reads done before strips overwrite region A

    for (int t = tstart; t < tend; t++) {
        const int s = (t - tstart) & 1;
        if (t + 1 < tend) {
            stage_W(s ^ 1, t + 1);
            stage_V(s ^ 1, t + 1);
            CP_COMMIT();
        }
        const __nv_bfloat16* sWh =
            reinterpret_cast<const __nv_bfloat16*>(smem + 13312 + s * 4096);
        const __nv_bfloat16* sWl = sWh + 1024;
        const float* sVf =
            reinterpret_cast<const float*>(smem + 21504 + s * 12288);
        const int c0 = t * 192;

#pragma unroll
        for (int mt = 0; mt < 4; mt++) {
            int r0 = mt * 16 + gid;
            uint32_t awh[4], awl[4];
            awh[0] = *reinterpret_cast<const uint32_t*>(&sWh[r0 * 16 + tig * 2]);
            awh[1] = *reinterpret_cast<const uint32_t*>(&sWh[(r0 + 8) * 16 + tig * 2]);
            awh[2] = *reinterpret_cast<const uint32_t*>(&sWh[r0 * 16 + 8 + tig * 2]);
            awh[3] = *reinterpret_cast<const uint32_t*>(&sWh[(r0 + 8) * 16 + 8 + tig * 2]);
            awl[0] = *reinterpret_cast<const uint32_t*>(&sWl[r0 * 16 + tig * 2]);
            awl[1] = *reinterpret_cast<const uint32_t*>(&sWl[(r0 + 8) * 16 + tig * 2]);
            awl[2] = *reinterpret_cast<const uint32_t*>(&sWl[r0 * 16 + 8 + tig * 2]);
            awl[3] = *reinterpret_cast<const uint32_t*>(&sWl[(r0 + 8) * 16 + 8 + tig * 2]);
#pragma unroll
            for (int ntl = 0; ntl < 3; ntl++) {
                float d[4] = {0.f, 0.f, 0.f, 0.f};
                mma16816(d, awh, fbh[ntl][0], fbh[ntl][1]);
                mma16816(d, awh, fbl[ntl][0], fbl[ntl][1]);
                mma16816(d, awl, fbh[ntl][0], fbh[ntl][1]);
                int col = ntl * 8 + tig * 2;
                *reinterpret_cast<float2*>(&strip[gid * 26 + col]) =
                    make_float2(d[0], d[1]);
                *reinterpret_cast<float2*>(&strip[(gid + 8) * 26 + col]) =
                    make_float2(d[2], d[3]);
            }
            __syncwarp();

            int v = mt * 16 + lv;
            int vg = t * 64 + v;
            if (vg < NVV) {
                const float* mv = &strip[lv * 26 + half * 12];
                float2 a0 = *reinterpret_cast<const float2*>(mv);
                float2 a1 = *reinterpret_cast<const float2*>(mv + 2);
                float2 a2 = *reinterpret_cast<const float2*>(mv + 4);
                float2 a3 = *reinterpret_cast<const float2*>(mv + 6);
                float2 a4 = *reinterpret_cast<const float2*>(mv + 8);
                float2 a5 = *reinterpret_cast<const float2*>(mv + 10);
                const float* vp = &sVf[bq * 192 + v * 3];
                float x = vp[0], yv = vp[1], z = vp[2];
                float o0 = fmaf(a0.x, x, fmaf(a0.y, yv, fmaf(a1.x, z, a1.y)));
                float o1 = fmaf(a2.x, x, fmaf(a2.y, yv, fmaf(a3.x, z, a3.y)));
                float o2 = fmaf(a4.x, x, fmaf(a4.y, yv, fmaf(a5.x, z, a5.y)));
                float* op = &outV[(size_t)bglob * CTOT + c0 + v * 3];
                op[0] = o0; op[1] = o1; op[2] = o2;

                int tp = -1;
                if (vg == 745) tp = 4; else if (vg == 317) tp = 8;
                else if (vg == 444) tp = 12; else if (vg == 556) tp = 16;
                else if (vg == 673) tp = 20;
                if (tp >= 0) {
                    outJ[(bglob * 21 + tp) * 3 + 0] = o0;
                    outJ[(bglob * 21 + tp) * 3 + 1] = o1;
                    outJ[(bglob * 21 + tp) * 3 + 2] = o2;
                }
            }
            __syncwarp();
        }

        if (t + 1 < tend) CP_WAIT(0);
        __syncthreads();
    }
}

// ---------------------------------------------------------------------------
extern "C" void kernel_launch(void* const* d_in, const int* in_sizes, int n_in,
                              void* d_out, int out_size) {
    const float* grmt  = (const float*)d_in[0];
    const float* frmt  = (const float*)d_in[1];
    const float* shape = (const float*)d_in[2];
    const float* trans = (const float*)d_in[3];
    const float* vt    = (const float*)d_in[4];
    const float* sd    = (const float*)d_in[5];
    const float* jreg  = (const float*)d_in[6];
    const float* pd    = (const float*)d_in[7];
    const float* lbs   = (const float*)d_in[8];

    float* out  = (float*)d_out;
    float* outV = out;
    float* outJ = out + (size_t)BB * CTOT;

    static cudaStream_t sB = nullptr;
    static cudaEvent_t evRoot = nullptr, evB = nullptr;
    static bool attr_done = false;
    if (!attr_done) {
        cudaFuncSetAttribute(k3_gemm, cudaFuncAttributeMaxDynamicSharedMemorySize,
                             SM_K3);
        cudaFuncSetAttribute(k4_epi, cudaFuncAttributeMaxDynamicSharedMemorySize,
                             SM_K4);
        cudaStreamCreateWithFlags(&sB, cudaStreamNonBlocking);
        cudaEventCreateWithFlags(&evRoot, cudaEventDisableTiming);
        cudaEventCreateWithFlags(&evB, cudaEventDisableTiming);
        attr_done = true;
    }

    // fork: branch stream runs k0_small -> k2 concurrent with k0_AB -> k3
    cudaEventRecord(evRoot, 0);
    cudaStreamWaitEvent(sB, evRoot, 0);

    k0_small<<<68, 256, 0, sB>>>(vt, sd, jreg, lbs);
    k2_joints<<<BB / 4, 256, 0, sB>>>(grmt, frmt, shape, trans, outJ);
    cudaEventRecord(evB, sB);

    k0_AB<<<840, 256>>>(sd, pd, shape, frmt);
    k3_gemm<<<dim3(BB / 64, 13), 256, SM_K3>>>(vt);

    // join, then epilogue
    cudaStreamWaitEvent(0, evB, 0);
    k4_epi<<<dim3(BB / 16, 4), 256, SM_K4>>>(outV, outJ);
}

// round 16
// speedup vs baseline: 1.4187x; 1.4187x over previous
#include <cuda_runtime.h>
#include <cuda_bf16.h>
#include <cstdint>

#define BB    8192
#define NVV   778
#define NJJ   16
#define CTOT  2334
#define CPAD  2496          // 13 * 192
#define GK    160           // padded K (145 feat + 15 pad)
#define NVP   832           // 13 * 64 padded verts

// ---------------- device scratch (static; no runtime alloc) ----------------
__device__ __align__(16) float          g_V[(size_t)BB * CPAD];      // GEMM out + bias
__device__ __align__(16) __nv_bfloat16  g_A[BB * GK];
__device__ __align__(16) __nv_bfloat16  g_B[CPAD * GK];              // B^T [n][k]
__device__ __align__(16) __nv_bfloat16  g_Whi[NVP * 16];             // lbs hi/lo
__device__ __align__(16) __nv_bfloat16  g_Wlo[NVP * 16];
__device__ __align__(16) __nv_bfloat16  g_MH[(size_t)BB * 12 * 16];  // M'' hi [(b*12+m)*16+j]
__device__ __align__(16) __nv_bfloat16  g_ML[(size_t)BB * 12 * 16];  // M'' lo
__device__ __align__(16) float g_J0[NJJ * 3];
__device__ __align__(16) float g_JS[NJJ * 3 * 10];

__constant__ int c_par[16] = {0,0,1,2,0,4,5,0,7,8,0,10,11,0,13,14};
__constant__ int c_inv[16] = {0,5,6,7,9,10,11,17,18,19,13,14,15,1,2,3};

__device__ __forceinline__ void mma16816(float* d, const uint32_t* a,
                                         uint32_t b0, uint32_t b1) {
    asm volatile(
        "mma.sync.aligned.m16n8k16.row.col.f32.bf16.bf16.f32 "
        "{%0,%1,%2,%3}, {%4,%5,%6,%7}, {%8,%9}, {%0,%1,%2,%3};"
        : "+f"(d[0]), "+f"(d[1]), "+f"(d[2]), "+f"(d[3])
        : "r"(a[0]), "r"(a[1]), "r"(a[2]), "r"(a[3]), "r"(b0), "r"(b1));
}

__device__ __forceinline__ uint32_t smem_u32(const void* p) {
    uint32_t a;
    asm("{ .reg .u64 t; cvta.to.shared.u64 t, %1; cvt.u32.u64 %0, t; }"
        : "=r"(a) : "l"(p));
    return a;
}
// L1-bypassing 16B async copy
__device__ __forceinline__ void cpasync16(uint32_t dst, const void* src) {
    asm volatile("cp.async.cg.shared.global [%0], [%1], 16;"
                 :: "r"(dst), "l"(src));
}
#define CP_COMMIT()  asm volatile("cp.async.commit_group;" ::: "memory")
#define CP_WAIT(n)   asm volatile("cp.async.wait_group %0;" :: "n"(n) : "memory")

// ---------------------------------------------------------------------------
// K0_SMALL: [0,16): jreg contractions; [16,68): lbs hi/lo split
// ---------------------------------------------------------------------------
__global__ __launch_bounds__(256) void k0_small(const float* __restrict__ vt,
                                                const float* __restrict__ sd,
                                                const float* __restrict__ jreg,
                                                const float* __restrict__ lbs) {
    __shared__ float red[33 * 256];
    const int blk = blockIdx.x, tid = threadIdx.x;

    if (blk >= 16) {                        // ---- lbs hi/lo
        int idx = (blk - 16) * 256 + tid;
        if (idx >= NVP * 16) return;
        int v = idx >> 4, j = idx & 15;
        float w = (v < NVV) ? lbs[v * 16 + j] : 0.f;
        __nv_bfloat16 hi = __float2bfloat16_rn(w);
        __nv_bfloat16 lo = __float2bfloat16_rn(w - __bfloat162float(hi));
        g_Whi[idx] = hi;
        g_Wlo[idx] = lo;
        return;
    }
    // ---- joint regressor: one block per joint
    const int j = blk;
    float acc[33];
#pragma unroll
    for (int o = 0; o < 33; o++) acc[o] = 0.f;
    for (int v = tid; v < NVV; v += 256) {
        float w = jreg[j * NVV + v];
#pragma unroll
        for (int k = 0; k < 3; k++) {
            acc[k] += w * vt[v * 3 + k];
#pragma unroll
            for (int l = 0; l < 10; l++)
                acc[3 + k * 10 + l] += w * sd[(v * 3 + k) * 10 + l];
        }
    }
    for (int o = 0; o < 33; o++) red[o * 256 + tid] = acc[o];
    __syncthreads();
    if (tid < 33) {
        float s = 0.f;
        for (int i = 0; i < 256; i++) s += red[tid * 256 + i];
        if (tid < 3) g_J0[j * 3 + tid] = s;
        else {
            int o = tid - 3;
            int k = o / 10, l = o - k * 10;
            g_JS[(j * 3 + k) * 10 + l] = s;
        }
    }
}

// ---------------------------------------------------------------------------
// K0_AB: [0,640): A (8 elems/thread, 20 groups/row); [640,840): B
// ---------------------------------------------------------------------------
__global__ __launch_bounds__(256) void k0_AB(const float* __restrict__ sd,
                                             const float* __restrict__ pd,
                                             const float* __restrict__ shape,
                                             const float* __restrict__ finger) {
    const int blk = blockIdx.x, tid = threadIdx.x;

    if (blk < 640) {                        // ---- A: feat bf16 [B x 160], 8/thr
        int idx = blk * 256 + tid;          // < 163840
        int b = idx / 20, g = idx - b * 20;
        unsigned short hs[8];
#pragma unroll
        for (int i = 0; i < 8; i++) {
            int k = g * 8 + i;
            float val = 0.f;
            if (k < 10) val = shape[b * 10 + k];
            else if (k < 145) {
                int q = k - 10;
                val = finger[b * 135 + q];
                if (((q % 9) & 3) == 0) val -= 1.0f;
            }
            hs[i] = __bfloat16_as_ushort(__float2bfloat16_rn(val));
        }
        uint4 ph;
        ph.x = hs[0] | ((uint32_t)hs[1] << 16);
        ph.y = hs[2] | ((uint32_t)hs[3] << 16);
        ph.z = hs[4] | ((uint32_t)hs[5] << 16);
        ph.w = hs[6] | ((uint32_t)hs[7] << 16);
        *reinterpret_cast<uint4*>(&g_A[b * GK + g * 8]) = ph;
        return;
    }
    // ---- B^T bf16 [n][k]
    int q = blk - 640;
    int kg = q / 10, nb = q - kg * 10;      // kg 0..19
    int n = nb * 256 + tid;
    if (n >= CPAD) return;
    unsigned short hs[8];
#pragma unroll
    for (int i = 0; i < 8; i++) {
        int k = kg * 8 + i;
        float val = 0.f;
        if (n < CTOT) {
            if (k < 10)       val = sd[n * 10 + k];
            else if (k < 145) val = pd[(k - 10) * CTOT + n];
        }
        hs[i] = __bfloat16_as_ushort(__float2bfloat16_rn(val));
    }
    uint4 ph;
    ph.x = hs[0] | ((uint32_t)hs[1] << 16);
    ph.y = hs[2] | ((uint32_t)hs[3] << 16);
    ph.z = hs[4] | ((uint32_t)hs[5] << 16);
    ph.w = hs[6] | ((uint32_t)hs[7] << 16);
    *reinterpret_cast<uint4*>(&g_B[n * GK + kg * 8]) = ph;
}

// ---------------------------------------------------------------------------
// K2: joint chain — 4 batches per CTA; writes M'' as split-bf16 (b*12+m)x16
// ---------------------------------------------------------------------------
__device__ __forceinline__ void mul4(const float* a, float* d) {
    float t[16];
#pragma unroll
    for (int r = 0; r < 4; r++)
#pragma unroll
        for (int c = 0; c < 4; c++)
            t[r * 4 + c] = a[r * 4 + 0] * d[0 + c] + a[r * 4 + 1] * d[4 + c] +
                           a[r * 4 + 2] * d[8 + c] + a[r * 4 + 3] * d[12 + c];
#pragma unroll
    for (int i = 0; i < 16; i++) d[i] = t[i];
}

__global__ __launch_bounds__(256) void k2_joints(const float* __restrict__ grmt,
                          const float* __restrict__ frmt,
                          const float* __restrict__ shape,
                          const float* __restrict__ trans,
                          float* __restrict__ outJ) {
    __shared__ float sJ[4][16][3];
    __shared__ float sM[4][16][16];
    __shared__ float sF[4][136];
    __shared__ float sg[4][9], st[4][3], ssh[4][10];
    const int tid = threadIdx.x;
    const int bs = tid >> 6;
    const int tl = tid & 63;
    const int b = blockIdx.x * 4 + bs;
    const int b0 = blockIdx.x * 4;

    for (int i = tid; i < 540; i += 256) {
        int s = i / 135, q = i - s * 135;
        sF[s][q] = frmt[(b0 + s) * 135 + q];
    }
    if (tl < 9)  sg[bs][tl]  = grmt[b * 9 + tl];
    if (tl < 3)  st[bs][tl]  = trans[b * 3 + tl];
    if (tl < 10) ssh[bs][tl] = shape[b * 10 + tl];
    __syncthreads();

    if (tl < 48) {
        int j = tl / 3, k = tl - j * 3;
        float a = g_J0[j * 3 + k];
#pragma unroll
        for (int l = 0; l < 10; l++) a += ssh[bs][l] * g_JS[(j * 3 + k) * 10 + l];
        sJ[bs][j][k] = a;
    }
    __syncthreads();

    if (tl < 16) {
        int j = tl;
        float R[9];
        if (j == 0) {
            R[0]=1;R[1]=0;R[2]=0;R[3]=0;R[4]=1;R[5]=0;R[6]=0;R[7]=0;R[8]=1;
        } else {
#pragma unroll
            for (int i = 0; i < 9; i++) R[i] = sF[bs][(j - 1) * 9 + i];
        }
        float t0 = sJ[bs][j][0], t1 = sJ[bs][j][1], t2 = sJ[bs][j][2];
        if (j > 0) {
            int p = c_par[j];
            t0 -= sJ[bs][p][0]; t1 -= sJ[bs][p][1]; t2 -= sJ[bs][p][2];
        }
        float* m = sM[bs][j];
        m[0]=R[0]; m[1]=R[1]; m[2]=R[2];  m[3]=t0;
        m[4]=R[3]; m[5]=R[4]; m[6]=R[5];  m[7]=t1;
        m[8]=R[6]; m[9]=R[7]; m[10]=R[8]; m[11]=t2;
        m[12]=0.f; m[13]=0.f; m[14]=0.f;  m[15]=1.f;
    }
    __syncthreads();

    if (tl < 5) {
        int j = 1 + 3 * tl;
        mul4(sM[bs][0], sM[bs][j]);
        mul4(sM[bs][j], sM[bs][j + 1]);
        mul4(sM[bs][j + 1], sM[bs][j + 2]);
    }
    __syncthreads();

    if (tl < 16) {
        int j = tl;
        const float* m = sM[bs][j];
        float jt0 = m[3], jt1 = m[7], jt2 = m[11];
        float J0 = sJ[bs][j][0], J1 = sJ[bs][j][1], J2 = sJ[bs][j][2];
        float tc0 = jt0 - (m[0] * J0 + m[1] * J1 + m[2]  * J2);
        float tc1 = jt1 - (m[4] * J0 + m[5] * J1 + m[6]  * J2);
        float tc2 = jt2 - (m[8] * J0 + m[9] * J1 + m[10] * J2);
        float row[12];
        int jp = c_inv[j];
#pragma unroll
        for (int r = 0; r < 3; r++) {
            float a = sg[bs][r * 3 + 0], bb = sg[bs][r * 3 + 1], cc = sg[bs][r * 3 + 2];
            row[r * 4 + 0] = a * m[0] + bb * m[4] + cc * m[8];
            row[r * 4 + 1] = a * m[1] + bb * m[5] + cc * m[9];
            row[r * 4 + 2] = a * m[2] + bb * m[6] + cc * m[10];
            row[r * 4 + 3] = a * tc0  + bb * tc1  + cc * tc2 + st[bs][r];
            outJ[(b * 21 + jp) * 3 + r] = a * jt0 + bb * jt1 + cc * jt2 + st[bs][r];
        }
#pragma unroll
        for (int mm = 0; mm < 12; mm++) {
            float x = row[mm];
            __nv_bfloat16 hi = __float2bfloat16_rn(x);
            __nv_bfloat16 lo = __float2bfloat16_rn(x - __bfloat162float(hi));
            size_t off = ((size_t)b * 12 + mm) * 16 + j;
            g_MH[off] = hi;
            g_ML[off] = lo;
        }
    }
}

// ---------------------------------------------------------------------------
// K3: single-bf16 mma.sync GEMM, cp.async 2-stage pipeline -> g_V (+fp32 bias)
//   CTA: 256 thr, tile 64(b) x 96(n), K=160 in chunks 64+64+32. 3 CTAs/SM.
//   Stage: A 64x144B @0, B 96x144B @9216; stage 23040, x2 = 46080
//   Warps: 2 m-warps (32 rows) x 4 n-warps (24 cols, nt=3)
// ---------------------------------------------------------------------------
#define STG_SZ  23040
#define SM_K3   46080

__global__ __launch_bounds__(256, 3) void k3_gemm(const float* __restrict__ vt) {
    extern __shared__ __align__(16) char smem[];
    __shared__ float sBias[96];
    const uint32_t sbase = smem_u32(smem);
    const int tid = threadIdx.x;
    const int wid = tid >> 5, lane = tid & 31;
    const int wm = wid & 1, wn = wid >> 1;      // 2 m-warps x 4 n-warps
    const int gid = lane >> 2, tig = lane & 3;
    const int b0 = blockIdx.x * 64;
    const int t  = blockIdx.y;                  // 0..25, 96 cols each

    if (tid < 96) {
        int c = t * 96 + tid;
        sBias[tid] = (c < CTOT) ? vt[c] : 0.f;
    }

    // stage one K-chunk of width KC starting at koff into stage s
    auto stage_chunk = [&](int s, int koff, int KC) {
        const uint32_t stg = sbase + s * STG_SZ;
        const int perRow = KC >> 3;           // uint4s per row
        const int aTasks = 64 * perRow;
        const int total  = 160 * perRow;
        for (int i = tid; i < total; i += 256) {
            if (i < aTasks) {
                int r = i / perRow, q = i - r * perRow;
                cpasync16(stg + r * 144 + q * 16,
                          &g_A[(b0 + r) * GK + koff + q * 8]);
            } else {
                int i2 = i - aTasks;
                int r = i2 / perRow, q = i2 - r * perRow;
                cpasync16(stg + 9216 + r * 144 + q * 16,
                          &g_B[(t * 96 + r) * GK + koff + q * 8]);
            }
        }
    };

    float d[2][3][4];
#pragma unroll
    for (int mt = 0; mt < 2; mt++)
#pragma unroll
        for (int nt = 0; nt < 3; nt++)
#pragma unroll
            for (int q = 0; q < 4; q++) d[mt][nt][q] = 0.f;

    stage_chunk(0, 0, 64);  CP_COMMIT();
    stage_chunk(1, 64, 64); CP_COMMIT();

    auto mma_chunk = [&](int s, int KS) {
        const char* stg = smem + s * STG_SZ;
        for (int ks = 0; ks < KS; ks++) {
            const int kb = ks * 32 + tig * 4;
            uint32_t ah[2][4];
#pragma unroll
            for (int mt = 0; mt < 2; mt++) {
                int r0 = wm * 32 + mt * 16 + gid;
                const char* ph = stg + r0 * 144 + kb;
                ah[mt][0] = *(const uint32_t*)(ph);
                ah[mt][1] = *(const uint32_t*)(ph + 8 * 144);
                ah[mt][2] = *(const uint32_t*)(ph + 16);
                ah[mt][3] = *(const uint32_t*)(ph + 8 * 144 + 16);
            }
            uint32_t bh[3][2];
#pragma unroll
            for (int nt = 0; nt < 3; nt++) {
                int n0 = wn * 24 + nt * 8 + gid;
                const char* ph = stg + 9216 + n0 * 144 + kb;
                bh[nt][0] = *(const uint32_t*)(ph);
                bh[nt][1] = *(const uint32_t*)(ph + 16);
            }
#pragma unroll
            for (int mt = 0; mt < 2; mt++)
#pragma unroll
                for (int nt = 0; nt < 3; nt++)
                    mma16816(d[mt][nt], ah[mt], bh[nt][0], bh[nt][1]);
        }
    };

    CP_WAIT(1); __syncthreads();
    mma_chunk(0, 4);
    __syncthreads();
    stage_chunk(0, 128, 32); CP_COMMIT();
    CP_WAIT(1); __syncthreads();
    mma_chunk(1, 4);
    CP_WAIT(0); __syncthreads();
    mma_chunk(0, 2);

#pragma unroll
    for (int mt = 0; mt < 2; mt++) {
        int r0 = b0 + wm * 32 + mt * 16 + gid;
#pragma unroll
        for (int nt = 0; nt < 3; nt++) {
            int cl = wn * 24 + nt * 8 + tig * 2;
            int c = t * 96 + cl;
            float bx = sBias[cl], by = sBias[cl + 1];
            *reinterpret_cast<float2*>(&g_V[(size_t)r0 * CPAD + c]) =
                make_float2(d[mt][nt][0] + bx, d[mt][nt][1] + by);
            *reinterpret_cast<float2*>(&g_V[(size_t)(r0 + 8) * CPAD + c]) =
                make_float2(d[mt][nt][2] + bx, d[mt][nt][3] + by);
        }
    }
}

// ---------------------------------------------------------------------------
// K4: warp-autonomous LBS blend, 4 CTAs/SM (unchanged from R14)
// ---------------------------------------------------------------------------
#define SM_K4 46080

__global__ __launch_bounds__(256, 4) void k4_epi(float* __restrict__ outV,
                                                 float* __restrict__ outJ) {
    extern __shared__ __align__(16) char smem[];
    const uint32_t sbase = smem_u32(smem);
    __nv_bfloat16* sMh = reinterpret_cast<__nv_bfloat16*>(smem);
    __nv_bfloat16* sMl = reinterpret_cast<__nv_bfloat16*>(smem + 6144);

    const int tid = threadIdx.x;
    const int b0 = blockIdx.x * 16;
    const int y  = blockIdx.y;
    const int tstart = (y == 0) ? 0 : 1 + y * 3;      // {0,4,7,10}
    const int tend   = tstart + ((y == 0) ? 4 : 3);   // {4,7,10,13}

    auto stage_W = [&](int s, int t) {
        int split = tid >> 7, i2 = tid & 127;
        int row = i2 >> 1, half = i2 & 1;
        const __nv_bfloat16* src = split ? g_Wlo : g_Whi;
        cpasync16(sbase + 13312 + s * 4096 + split * 2048 +
                      (row * 16 + half * 8) * 2,
                  &src[(t * 64 + row) * 16 + half * 8]);
    };
    auto stage_V = [&](int s, int t) {
        for (int i = tid; i < 768; i += 256) {
            int r = i / 48, q = i - r * 48;
            cpasync16(sbase + 21504 + s * 12288 + (r * 192 + q * 4) * 4,
                      &g_V[(size_t)(b0 + r) * CPAD + t * 192 + q * 4]);
        }
    };

    // stage M'' (12KB into region A) + first W and V slices
    for (int i = tid; i < 768; i += 256) {
        int split = i / 384, i2 = i - split * 384;
        int n = i2 >> 1, half = i2 & 1;
        const __nv_bfloat16* src = split ? g_ML : g_MH;
        cpasync16(sbase + split * 6144 + (n * 16 + half * 8) * 2,
                  &src[((size_t)b0 * 12 + n) * 16 + half * 8]);
    }
    stage_W(0, tstart);
    stage_V(0, tstart);
    CP_COMMIT();
    CP_WAIT(0);
    __syncthreads();

    const int wid = tid >> 5, lane = tid & 31;
    const int gid = lane >> 2, tig = lane & 3;
    float* strip = reinterpret_cast<float*>(smem + wid * 1664);  // region A reuse
    const int half = lane >> 4, lv = lane & 15;
    const int bq = wid * 2 + half;
    const int bglob = b0 + bq;

    // hoist B fragments (M'' columns) — tile-invariant
    uint32_t fbh[3][2], fbl[3][2];
#pragma unroll
    for (int ntl = 0; ntl < 3; ntl++) {
        int n0 = wid * 24 + ntl * 8 + gid;
        fbh[ntl][0] = *reinterpret_cast<const uint32_t*>(&sMh[n0 * 16 + tig * 2]);
        fbh[ntl][1] = *reinterpret_cast<const uint32_t*>(&sMh[n0 * 16 + 8 + tig * 2]);
        fbl[ntl][0] = *reinterpret_cast<const uint32_t*>(&sMl[n0 * 16 + tig * 2]);
        fbl[ntl][1] = *reinterpret_cast<const uint32_t*>(&sMl[n0 * 16 + 8 + tig * 2]);
    }
    __syncthreads();   // all M'' reads done before strips overwrite region A

    for (int t = tstart; t < tend; t++) {
        const int s = (t - tstart) & 1;
        if (t + 1 < tend) {
            stage_W(s ^ 1, t + 1);
            stage_V(s ^ 1, t + 1);
            CP_COMMIT();
        }
        const __nv_bfloat16* sWh =
            reinterpret_cast<const __nv_bfloat16*>(smem + 13312 + s * 4096);
        const __nv_bfloat16* sWl = sWh + 1024;
        const float* sVf =
            reinterpret_cast<const float*>(smem + 21504 + s * 12288);
        const int c0 = t * 192;

#pragma unroll
        for (int mt = 0; mt < 4; mt++) {
            int r0 = mt * 16 + gid;
            uint32_t awh[4], awl[4];
            awh[0] = *reinterpret_cast<const uint32_t*>(&sWh[r0 * 16 + tig * 2]);
            awh[1] = *reinterpret_cast<const uint32_t*>(&sWh[(r0 + 8) * 16 + tig * 2]);
            awh[2] = *reinterpret_cast<const uint32_t*>(&sWh[r0 * 16 + 8 + tig * 2]);
            awh[3] = *reinterpret_cast<const uint32_t*>(&sWh[(r0 + 8) * 16 + 8 + tig * 2]);
            awl[0] = *reinterpret_cast<const uint32_t*>(&sWl[r0 * 16 + tig * 2]);
            awl[1] = *reinterpret_cast<const uint32_t*>(&sWl[(r0 + 8) * 16 + tig * 2]);
            awl[2] = *reinterpret_cast<const uint32_t*>(&sWl[r0 * 16 + 8 + tig * 2]);
            awl[3] = *reinterpret_cast<const uint32_t*>(&sWl[(r0 + 8) * 16 + 8 + tig * 2]);
#pragma unroll
            for (int ntl = 0; ntl < 3; ntl++) {
                float d[4] = {0.f, 0.f, 0.f, 0.f};
                mma16816(d, awh, fbh[ntl][0], fbh[ntl][1]);
                mma16816(d, awh, fbl[ntl][0], fbl[ntl][1]);
                mma16816(d, awl, fbh[ntl][0], fbh[ntl][1]);
                int col = ntl * 8 + tig * 2;
                *reinterpret_cast<float2*>(&strip[gid * 26 + col]) =
                    make_float2(d[0], d[1]);
                *reinterpret_cast<float2*>(&strip[(gid + 8) * 26 + col]) =
                    make_float2(d[2], d[3]);
            }
            __syncwarp();

            int v = mt * 16 + lv;
            int vg = t * 64 + v;
            if (vg < NVV) {
                const float* mv = &strip[lv * 26 + half * 12];
                float2 a0 = *reinterpret_cast<const float2*>(mv);
                float2 a1 = *reinterpret_cast<const float2*>(mv + 2);
                float2 a2 = *reinterpret_cast<const float2*>(mv + 4);
                float2 a3 = *reinterpret_cast<const float2*>(mv + 6);
                float2 a4 = *reinterpret_cast<const float2*>(mv + 8);
                float2 a5 = *reinterpret_cast<const float2*>(mv + 10);
                const float* vp = &sVf[bq * 192 + v * 3];
                float x = vp[0], yv = vp[1], z = vp[2];
                float o0 = fmaf(a0.x, x, fmaf(a0.y, yv, fmaf(a1.x, z, a1.y)));
                float o1 = fmaf(a2.x, x, fmaf(a2.y, yv, fmaf(a3.x, z, a3.y)));
                float o2 = fmaf(a4.x, x, fmaf(a4.y, yv, fmaf(a5.x, z, a5.y)));
                float* op = &outV[(size_t)bglob * CTOT + c0 + v * 3];
                op[0] = o0; op[1] = o1; op[2] = o2;

                int tp = -1;
                if (vg == 745) tp = 4; else if (vg == 317) tp = 8;
                else if (vg == 444) tp = 12; else if (vg == 556) tp = 16;
                else if (vg == 673) tp = 20;
                if (tp >= 0) {
                    outJ[(bglob * 21 + tp) * 3 + 0] = o0;
                    outJ[(bglob * 21 + tp) * 3 + 1] = o1;
                    outJ[(bglob * 21 + tp) * 3 + 2] = o2;
                }
            }
            __syncwarp();
        }

        if (t + 1 < tend) CP_WAIT(0);
        __syncthreads();
    }
}

// ---------------------------------------------------------------------------
extern "C" void kernel_launch(void* const* d_in, const int* in_sizes, int n_in,
                              void* d_out, int out_size) {
    const float* grmt  = (const float*)d_in[0];
    const float* frmt  = (const float*)d_in[1];
    const float* shape = (const float*)d_in[2];
    const float* trans = (const float*)d_in[3];
    const float* vt    = (const float*)d_in[4];
    const float* sd    = (const float*)d_in[5];
    const float* jreg  = (const float*)d_in[6];
    const float* pd    = (const float*)d_in[7];
    const float* lbs   = (const float*)d_in[8];

    float* out  = (float*)d_out;
    float* outV = out;
    float* outJ = out + (size_t)BB * CTOT;

    static cudaStream_t sB = nullptr;
    static cudaEvent_t evRoot = nullptr, evB = nullptr;
    static bool attr_done = false;
    if (!attr_done) {
        cudaFuncSetAttribute(k3_gemm, cudaFuncAttributeMaxDynamicSharedMemorySize,
                             SM_K3);
        cudaFuncSetAttribute(k4_epi, cudaFuncAttributeMaxDynamicSharedMemorySize,
                             SM_K4);
        cudaStreamCreateWithFlags(&sB, cudaStreamNonBlocking);
        cudaEventCreateWithFlags(&evRoot, cudaEventDisableTiming);
        cudaEventCreateWithFlags(&evB, cudaEventDisableTiming);
        attr_done = true;
    }

    // fork: branch stream runs k0_small -> k2 concurrent with k0_AB -> k3
    cudaEventRecord(evRoot, 0);
    cudaStreamWaitEvent(sB, evRoot, 0);

    k0_small<<<68, 256, 0, sB>>>(vt, sd, jreg, lbs);
    k2_joints<<<BB / 4, 256, 0, sB>>>(grmt, frmt, shape, trans, outJ);
    cudaEventRecord(evB, sB);

    k0_AB<<<840, 256>>>(sd, pd, shape, frmt);
    k3_gemm<<<dim3(BB / 64, 26), 256, SM_K3>>>(vt);

    // join, then epilogue
    cudaStreamWaitEvent(0, evB, 0);
    k4_epi<<<dim3(BB / 16, 4), 256, SM_K4>>>(outV, outJ);
}